// round 12
// baseline (speedup 1.0000x reference)
#include <cuda_runtime.h>
#include <math.h>

#define HH 1024
#define WW 1024
#define PLANES 24           // 8 batch * 3 channels
#define RAD 25
#define TAPS 51

#define XC 128              // output cols per block
#define YS 256              // output rows per block
#define IR 16               // rows processed per iteration
#define NITER 21            // H active i=0..19 (320 halo rows), V active i=5..20
#define LAG 5               // V(i) consumes group g = i-LAG
#define RING 96
#define MIR 66              // mirrored rows: V window span = 66
#define HBR (RING + MIR)    // 162
#define XW 178              // staged x cols (128 + 2*25)
#define XP 184              // sx pitch (floats), float4-aligned

// ---------------- compile-time gaussian weights ---------------------------
struct WTab { float w[TAPS]; };

__host__ __device__ constexpr double cexp_series(double x) {
    double term = 1.0, sum = 1.0;
    for (int i = 1; i < 40; ++i) { term *= x / (double)i; sum += term; }
    return sum;
}

__host__ __device__ constexpr WTab make_wtab() {
    WTab t{};
    double g[TAPS] = {};
    double s = 0.0;
    for (int i = 0; i < TAPS; ++i) {
        double d = (double)(i - RAD);
        g[i] = cexp_series(-d * d / (2.0 * 15.0 * 15.0));
        s += g[i];
    }
    for (int i = 0; i < TAPS; ++i) t.w[i] = (float)(g[i] / s);
    return t;
}

__constant__ WTab c_wt = make_wtab();

// ---------------- packed f32x2 helpers ------------------------------------
__device__ __forceinline__ unsigned long long pk2(float a, float b) {
    unsigned long long r;
    asm("mov.b64 %0, {%1, %2};" : "=l"(r) : "f"(a), "f"(b));
    return r;
}
__device__ __forceinline__ void upk2(unsigned long long v, float& a, float& b) {
    asm("mov.b64 {%0, %1}, %2;" : "=f"(a), "=f"(b) : "l"(v));
}
__device__ __forceinline__ unsigned long long ffma2(unsigned long long a,
                                                    unsigned long long b,
                                                    unsigned long long c) {
    unsigned long long d;
    asm("fma.rn.f32x2 %0, %1, %2, %3;" : "=l"(d) : "l"(a), "l"(b), "l"(c));
    return d;
}

extern __shared__ float sm[];  // [wb: 104f | hb: 162*128 | sx: 16*184]

__global__ void __launch_bounds__(256, 2) fused(const float* __restrict__ x,
                                                const float* __restrict__ amt_p,
                                                float* __restrict__ out) {
    unsigned long long* wb = (unsigned long long*)sm;   // 51 weight pairs
    float* hb = sm + 104;                               // ring+mirror, 162 x 128
    float* sx = hb + HBR * XC;                          // 16 x 184

    const int t = threadIdx.x;
    const int plane = blockIdx.z;
    const int x0 = blockIdx.x * XC;
    const int yb = blockIdx.y * YS;
    const float* xp = x + (size_t)plane * HH * WW;
    float* op = out + (size_t)plane * HH * WW;

    if (t < TAPS) wb[t] = pk2(c_wt.w[t], c_wt.w[t]);

    const float kk = 1.2f * (0.4f / (1.0f + expf(-amt_p[0])));

    // staging role: 16 threads per row, 12 col slots each
    const int srow  = t >> 4;
    const int scol0 = t & 15;

    // role split
    const bool isV = (t < 128);
    // H (warps 4-7): 16 colgroups x 8 rowbases; thread does rows {hrr, hrr+8} x 8 cols
    const int ht  = t - 128;
    const int hc0 = 8 * (ht & 15);
    const int hrr = (ht >> 4) & 7;
    // V (warps 0-3): 64 col-pairs x 2 rowgroups of 8 rows
    const int cp = t & 63;
    const int rg = (t >> 6) & 1;

    constexpr WTab WT = make_wtab();

    // prefetch x rows for iter 0
    float px[12];
    {
        const int gy = yb - RAD + srow;
        const bool yok = ((unsigned)gy < HH);
        #pragma unroll
        for (int e = 0; e < 12; ++e) {
            const int c  = scol0 + 16 * e;
            const int gx = x0 - RAD + c;
            px[e] = (yok && c < XW && (unsigned)gx < WW)
                    ? __ldg(&xp[(size_t)gy * WW + gx]) : 0.0f;
        }
    }

    int rbh = 0;    // (IR*i)      mod RING at iter start
    int rbv = 16;   // (IR*(i-LAG)) mod RING at iter start (wraps to 0 at i=5)

    #pragma unroll 1
    for (int i = 0; i < NITER; ++i) {
        // ---- stage prefetched x rows (H active iters only) ------------------
        if (i < NITER - 1) {
            #pragma unroll
            for (int e = 0; e < 12; ++e) {
                const int c = scol0 + 16 * e;
                if (c < XP) sx[srow * XP + c] = px[e];
            }
        }
        __syncthreads();   // sx ready; hb(i-1) visible to V

        // ---- prefetch next iteration's x rows -------------------------------
        if (i + 1 < NITER - 1) {
            const int gy = yb - RAD + IR * (i + 1) + srow;
            const bool yok = ((unsigned)gy < HH);
            #pragma unroll
            for (int e = 0; e < 12; ++e) {
                const int c  = scol0 + 16 * e;
                const int gx = x0 - RAD + c;
                px[e] = (yok && c < XW && (unsigned)gx < WW)
                        ? __ldg(&xp[(size_t)gy * WW + gx]) : 0.0f;
            }
        }

        if (!isV) {
            // ================= H pass: 2 rows x 8 cols, FFMA-imm =============
            if (i < NITER - 1) {
                const float4* A4 = (const float4*)(sx + hrr * XP);
                const float4* B4 = (const float4*)(sx + (hrr + 8) * XP);
                const int m0 = hc0 >> 2;

                float4 qa0 = A4[m0], qa1 = A4[m0+1], qa2 = A4[m0+2], qa3 = A4[m0+3];
                float4 qb0 = B4[m0], qb1 = B4[m0+1], qb2 = B4[m0+2], qb3 = B4[m0+3];
                float accA[8], accB[8];
                #pragma unroll
                for (int o = 0; o < 8; ++o) { accA[o] = 0.f; accB[o] = 0.f; }

                #pragma unroll
                for (int m = 0; m < 13; ++m) {
                    const float fa[12] = {qa0.x,qa0.y,qa0.z,qa0.w,
                                          qa1.x,qa1.y,qa1.z,qa1.w,
                                          qa2.x,qa2.y,qa2.z,qa2.w};
                    const float fb[12] = {qb0.x,qb0.y,qb0.z,qb0.w,
                                          qb1.x,qb1.y,qb1.z,qb1.w,
                                          qb2.x,qb2.y,qb2.z,qb2.w};
                    #pragma unroll
                    for (int j = 0; j < 4; ++j) {
                        const int k = 4 * m + j;
                        if (k <= 2 * RAD) {
                            #pragma unroll
                            for (int o = 0; o < 8; ++o) {
                                accA[o] += WT.w[k] * fa[j + o];   // FFMA-imm
                                accB[o] += WT.w[k] * fb[j + o];
                            }
                        }
                    }
                    qa0 = qa1; qa1 = qa2; qa2 = qa3;
                    qb0 = qb1; qb1 = qb2; qb2 = qb3;
                    if (m + 4 <= 14) { qa3 = A4[m0 + m + 4]; qb3 = B4[m0 + m + 4]; }
                }

                // store both rows (+ mirror)
                #pragma unroll
                for (int rr2 = 0; rr2 < 2; ++rr2) {
                    const int r = hrr + 8 * rr2;
                    int slot = rbh + r;
                    if (slot >= RING) slot -= RING;
                    const float* A = rr2 ? accB : accA;
                    float4 lo = make_float4(A[0], A[1], A[2], A[3]);
                    float4 hi = make_float4(A[4], A[5], A[6], A[7]);
                    float* dst = hb + slot * XC + hc0;
                    *(float4*)dst       = lo;
                    *(float4*)(dst + 4) = hi;
                    if (slot < MIR) {
                        float* d2 = dst + RING * XC;
                        *(float4*)d2       = lo;
                        *(float4*)(d2 + 4) = hi;
                    }
                }
            }
        } else {
            // ================= V pass + blend: 8 rows x 2 cols, FFMA2 ========
            if (i >= LAG) {
                const int bs = rbv + 8 * rg;          // <= 88; reads bs..bs+57 < 162
                const float* hbase = hb + (size_t)bs * XC + 2 * cp;

                unsigned long long win[16];
                #pragma unroll
                for (int j = 0; j < 11; ++j)
                    win[j] = *(const unsigned long long*)(hbase + j * XC);

                unsigned long long acc[8];
                #pragma unroll
                for (int ii = 0; ii < 8; ++ii) acc[ii] = 0ull;

                #pragma unroll
                for (int d = 0; d <= 2 * RAD; ++d) {
                    if (d + 11 <= 57)
                        win[(d + 11) & 15] =
                            *(const unsigned long long*)(hbase + (d + 11) * XC);
                    const unsigned long long wd = wb[d];
                    #pragma unroll
                    for (int ii = 0; ii < 8; ++ii)
                        acc[ii] = ffma2(win[(d + ii) & 15], wd, acc[ii]);
                }

                const int vy0 = IR * (i - LAG) + 8 * rg;
                #pragma unroll
                for (int ii = 0; ii < 8; ++ii) {
                    const size_t off = (size_t)(yb + vy0 + ii) * WW + x0 + 2 * cp;
                    const float2 xv = *(const float2*)(xp + off);
                    float b0, b1;
                    upk2(acc[ii], b0, b1);
                    float r0 = fmaf(b0 * kk, 1.0f - xv.x, xv.x);
                    float r1 = fmaf(b1 * kk, 1.0f - xv.y, xv.y);
                    r0 = fminf(fmaxf(r0, 0.0f), 1.0f);
                    r1 = fminf(fmaxf(r1, 0.0f), 1.0f);
                    *(float2*)(op + off) = make_float2(r0, r1);
                }
            }
        }
        __syncthreads();   // H done with sx; V done with hb window

        rbh += IR; if (rbh >= RING) rbh -= RING;
        rbv += IR; if (rbv >= RING) rbv -= RING;
    }
}

extern "C" void kernel_launch(void* const* d_in, const int* in_sizes, int n_in,
                              void* d_out, int out_size) {
    const float* x   = (const float*)d_in[0];
    const float* amt = (const float*)d_in[1];
    float* out = (float*)d_out;

    const int smem = (104 + HBR * XC + IR * XP) * (int)sizeof(float);  // 95136 B
    cudaFuncSetAttribute(fused, cudaFuncAttributeMaxDynamicSharedMemorySize, smem);

    dim3 grid(WW / XC, HH / YS, PLANES);   // (8, 4, 24) = 768 blocks
    fused<<<grid, 256, smem>>>(x, amt, out);
}